// round 6
// baseline (speedup 1.0000x reference)
#include <cuda_runtime.h>

#define NA 192
#define TT 80
#define NC 5
#define ISLICE 24
#define NPAIR ((size_t)NA * NA)

// Block: 192 threads, j = tid. Grid: (T, NA/ISLICE) = (80, 8).
// Phase 1: all 192 threads compute world circle centers for this t into smem.
// Phase 2: each thread owns column j; loops over a slice of i rows.
//   d^2(i,j,c,d) = s_i[c] + s_j[d] - 2 * <w_i[c], w_j[d]>
//   min over (c,d); penalty = 1 - sqrt(min)/pd; mask = (sqrt(min) <= pd) && offdiag.
__global__ __launch_bounds__(NA) void vehcoll_kernel(
    const float4* __restrict__ traj,        // [NA*T] as float4 (x,y,hx,hy)
    const float4* __restrict__ cent,        // [NA*NC] as float4 (cx,cy,1,0)
    const float*  __restrict__ pd,          // [NA*NA]
    const int*    __restrict__ offd,        // [NA*NA] bool upcast to int32 by harness
    float* __restrict__ out_pen,            // [T*NA*NA] float32
    float* __restrict__ out_mask)           // [T*NA*NA] float32 (0.0 / 1.0)
{
    __shared__ float4 sw[NA * NC];   // (wx, wy, wx^2+wy^2, pad)

    const int t   = blockIdx.x;
    const int tid = threadIdx.x;

    // ---- Phase 1: world-frame circle centers for timestep t ----
    {
        const int a = tid;  // one agent per thread
        float4 tr = traj[a * TT + t];
        float hx = tr.z, hy = tr.w;
        float inv = rsqrtf(fmaf(hx, hx, hy * hy));
        hx *= inv;
        hy *= inv;
#pragma unroll
        for (int c = 0; c < NC; c++) {
            float4 cc = cent[a * NC + c];
            float wx = tr.x + hx * cc.x - hy * cc.y;
            float wy = tr.y + hy * cc.x + hx * cc.y;
            sw[a * NC + c] = make_float4(wx, wy, fmaf(wx, wx, wy * wy), 0.0f);
        }
    }
    __syncthreads();

    // ---- Phase 2: pairwise min-distance over the i-slice ----
    const int j = tid;
    float wjx[NC], wjy[NC], sj[NC];
#pragma unroll
    for (int d = 0; d < NC; d++) {
        float4 w = sw[j * NC + d];
        wjx[d] = w.x; wjy[d] = w.y; sj[d] = w.z;
    }

    const int    ibase = blockIdx.y * ISLICE;
    const size_t tbase = (size_t)t * NPAIR;

#pragma unroll 2
    for (int ii = 0; ii < ISLICE; ii++) {
        const int i = ibase + ii;
        float minv = 3.4e38f;
#pragma unroll
        for (int c = 0; c < NC; c++) {
            float4 wi = sw[i * NC + c];   // broadcast LDS.128 (uniform across warp)
            // p_d = s_j[d] - 2 * dot(w_i[c], w_j[d])
            float p0 = fmaf(-2.0f, fmaf(wi.y, wjy[0], wi.x * wjx[0]), sj[0]);
            float p1 = fmaf(-2.0f, fmaf(wi.y, wjy[1], wi.x * wjx[1]), sj[1]);
            float p2 = fmaf(-2.0f, fmaf(wi.y, wjy[2], wi.x * wjx[2]), sj[2]);
            float p3 = fmaf(-2.0f, fmaf(wi.y, wjy[3], wi.x * wjx[3]), sj[3]);
            float p4 = fmaf(-2.0f, fmaf(wi.y, wjy[4], wi.x * wjx[4]), sj[4]);
            float m  = fminf(fminf(fminf(p0, p1), fminf(p2, p3)), p4);
            minv = fminf(minv, wi.z + m);  // + s_i[c]
        }
        const float dd = sqrtf(fmaxf(minv, 0.0f));
        const int   pidx = i * NA + j;
        const float p = pd[pidx];
        const float pen = 1.0f - __fdividef(dd, p);
        const bool  col = (dd <= p) && (offd[pidx] != 0);

        out_pen [tbase + pidx] = pen;
        out_mask[tbase + pidx] = col ? 1.0f : 0.0f;
    }
}

extern "C" void kernel_launch(void* const* d_in, const int* in_sizes, int n_in,
                              void* d_out, int out_size) {
    const float4* traj = (const float4*)d_in[0];        // [192,80,4]
    const float4* cent = (const float4*)d_in[1];        // [192,5,4]
    const float*  pd   = (const float*)d_in[2];         // [192,192]
    const int*    offd = (const int*)d_in[3];           // [192,192] int32

    float* out_pen  = (float*)d_out;
    float* out_mask = out_pen + (size_t)TT * NPAIR;

    dim3 grid(TT, NA / ISLICE);
    vehcoll_kernel<<<grid, NA>>>(traj, cent, pd, offd, out_pen, out_mask);
}

// round 7
// speedup vs baseline: 1.3503x; 1.3503x over previous
#include <cuda_runtime.h>

#define NA 192
#define TT 80
#define NC 5
#define ISLICE 12
#define NPAIR ((size_t)NA * NA)

// Block: 192 threads, j = tid. Grid: (T, NA/ISLICE) = (80, 16) = 1280 blocks.
// Phase 1: all 192 threads compute world circle centers for this t into smem.
// Phase 2: each thread owns column j; loops over a slice of i rows.
//   d^2(i,j,c,d) = s_i[c] + (s_j[d] - 2*wjx[d]*wix - 2*wjy[d]*wiy)
//               = s_i[c] + fma(wix, uj[d], fma(wiy, vj[d], sj[d]))
//   with uj = -2*wjx, vj = -2*wjy precomputed per thread (2 FFMA per (c,d)).
__global__ __launch_bounds__(NA) void vehcoll_kernel(
    const float4* __restrict__ traj,        // [NA*T] as float4 (x,y,hx,hy)
    const float4* __restrict__ cent,        // [NA*NC] as float4 (cx,cy,1,0)
    const float*  __restrict__ pd,          // [NA*NA]
    const int*    __restrict__ offd,        // [NA*NA] bool upcast to int32
    float* __restrict__ out_pen,            // [T*NA*NA] float32
    float* __restrict__ out_mask)           // [T*NA*NA] float32 (0.0 / 1.0)
{
    __shared__ float4 sw[NA * NC];   // (wx, wy, wx^2+wy^2, pad)

    const int t   = blockIdx.x;
    const int tid = threadIdx.x;

    // ---- Phase 1: world-frame circle centers for timestep t ----
    {
        const int a = tid;
        float4 tr = traj[a * TT + t];
        float hx = tr.z, hy = tr.w;
        float inv = rsqrtf(fmaf(hx, hx, hy * hy));
        hx *= inv;
        hy *= inv;
#pragma unroll
        for (int c = 0; c < NC; c++) {
            float4 cc = cent[a * NC + c];
            float wx = tr.x + hx * cc.x - hy * cc.y;
            float wy = tr.y + hy * cc.x + hx * cc.y;
            sw[a * NC + c] = make_float4(wx, wy, fmaf(wx, wx, wy * wy), 0.0f);
        }
    }
    __syncthreads();

    // ---- Phase 2: per-thread j-column constants ----
    const int j = tid;
    float uj[NC], vj[NC], sj[NC];
#pragma unroll
    for (int d = 0; d < NC; d++) {
        float4 w = sw[j * NC + d];
        uj[d] = -2.0f * w.x;
        vj[d] = -2.0f * w.y;
        sj[d] = w.z;
    }

    const int ibase = blockIdx.y * ISLICE;
    // running pointers (avoid per-iteration IMAD index math)
    const size_t base0 = (size_t)t * NPAIR + (size_t)ibase * NA + j;
    const float* pdp   = pd   + ibase * NA + j;
    const int*   offp  = offd + ibase * NA + j;
    float* penp  = out_pen  + base0;
    float* maskp = out_mask + base0;
    const float4* swi = sw + ibase * NC;

#pragma unroll 4
    for (int ii = 0; ii < ISLICE; ii++) {
        float minv = 3.4e38f;
#pragma unroll
        for (int c = 0; c < NC; c++) {
            float4 wi = swi[ii * NC + c];   // broadcast LDS.128 (uniform across warp)
            float p0 = fmaf(wi.x, uj[0], fmaf(wi.y, vj[0], sj[0]));
            float p1 = fmaf(wi.x, uj[1], fmaf(wi.y, vj[1], sj[1]));
            float p2 = fmaf(wi.x, uj[2], fmaf(wi.y, vj[2], sj[2]));
            float p3 = fmaf(wi.x, uj[3], fmaf(wi.y, vj[3], sj[3]));
            float p4 = fmaf(wi.x, uj[4], fmaf(wi.y, vj[4], sj[4]));
            float m  = fminf(fminf(fminf(p0, p1), fminf(p2, p3)), p4);
            minv = fminf(minv, wi.z + m);  // + s_i[c]
        }
        const float dd = sqrtf(fmaxf(minv, 0.0f));
        const float p = pdp[ii * NA];
        const float pen = 1.0f - __fdividef(dd, p);
        const bool  col = (dd <= p) && (offp[ii * NA] != 0);

        penp [ii * NA] = pen;
        maskp[ii * NA] = col ? 1.0f : 0.0f;
    }
}

extern "C" void kernel_launch(void* const* d_in, const int* in_sizes, int n_in,
                              void* d_out, int out_size) {
    const float4* traj = (const float4*)d_in[0];        // [192,80,4]
    const float4* cent = (const float4*)d_in[1];        // [192,5,4]
    const float*  pd   = (const float*)d_in[2];         // [192,192]
    const int*    offd = (const int*)d_in[3];           // [192,192] int32

    float* out_pen  = (float*)d_out;
    float* out_mask = out_pen + (size_t)TT * NPAIR;

    dim3 grid(TT, NA / ISLICE);
    vehcoll_kernel<<<grid, NA>>>(traj, cent, pd, offd, out_pen, out_mask);
}